// round 5
// baseline (speedup 1.0000x reference)
#include <cuda_runtime.h>
#include <cstdint>

// ---------------------------------------------------------------------------
// Problem constants
// ---------------------------------------------------------------------------
#define NN    512
#define TT    64
#define DIN   1024
#define DOUT  1024
#define MTOT  (NN * TT)          // 32768

// Tiling: CTA 128x128, 256 threads, 8x8 per thread, KC=32, double-buffered.
#define KC     32
#define KTILES (DIN / KC)        // 32

// Dynamic smem: pipeline buffers (2 x (As+Bs)) reused as epilogue staging.
// As/Bs stage: [KC][132] floats = 32*132*4 = 16896 B each.
#define STAGE_FLOATS (KC * 132)
#define PIPE_FLOATS  (4 * STAGE_FLOATS)        // 2 buffers x (A + B) = 67584 B
#define STG_PITCH    129                       // staging [o:128][pitch][m:128]
#define SMEM_BYTES   (PIPE_FLOATS * 4)         // 67584 >= 128*129*4 = 66048

// ---------------------------------------------------------------------------
// Device scratch (sanctioned: __device__ globals)
// ---------------------------------------------------------------------------
__device__ float g_wn[DOUT * DIN];          // BN-folded weight (bit-same as R1)
__device__ float g_bstep[DOUT];             // b_norm / T

// ---------------------------------------------------------------------------
// Prep: fold BN into weights.  ratio = gamma / sqrt(var)  (no eps, per source)
// Arithmetic identical to the R1 kernel (single mul per weight).
// ---------------------------------------------------------------------------
__global__ void prep_kernel(const float* __restrict__ w,
                            const float* __restrict__ bias,
                            const float* __restrict__ gamma,
                            const float* __restrict__ beta,
                            const float* __restrict__ mean,
                            const float* __restrict__ var) {
    const int o = blockIdx.x;            // 1024 blocks
    const float ratio = gamma[o] / sqrtf(var[o]);
    if (threadIdx.x == 0) {
        g_bstep[o] = ((bias[o] - mean[o]) * ratio + beta[o]) * (1.0f / (float)TT);
    }
    const float* wr = w + (size_t)o * DIN;
    float* wo = g_wn + (size_t)o * DIN;
    for (int k = threadIdx.x; k < DIN; k += blockDim.x) {
        wo[k] = wr[k] * ratio;
    }
}

// ---------------------------------------------------------------------------
// Fused SGEMM + IF scan.
// C[m, o] = serial-k fp32 fma chain of A[m,k] * Wn[o,k]  (bit-identical to R1:
// acc starts at 0, k ascends 0..1023, one fmaf per k).
// Then the CTA's 128 m-rows = 2 complete (n, t=0..63) groups: stage [o][m] in
// smem and run the integrate-and-fire scan in-CTA. No g_pot round trip.
//
// Thread/warp layout identical to R1:
//   warps 4(rows) x 2(cols); rbase = wr*32 + (lane>>3)*4 (+0/+16)
//   cbase = wc*64 + (lane&7)*4 (+0/+32)  -> conflict-free LDS.128 groups.
// ---------------------------------------------------------------------------
__global__ __launch_bounds__(256, 2)
void gemm_if_kernel(const float* __restrict__ A,
                    float* __restrict__ spike_out,
                    float* __restrict__ count_out) {
    extern __shared__ __align__(16) float smem[];
    // Pipeline views: buf b: A at smem + b*2*STAGE_FLOATS, B right after.
    const int tid  = threadIdx.x;
    const int warp = tid >> 5;
    const int lane = tid & 31;
    const int wr   = warp >> 1;                      // 0..3
    const int wc   = warp & 1;                       // 0..1
    const int rbase = wr * 32 + ((lane >> 3) << 2);
    const int cbase = wc * 64 + ((lane & 7) << 2);

    const int m0 = blockIdx.x * 128;
    const int o0 = blockIdx.y * 128;

    const float* gA = A    + (size_t)m0 * DIN;
    const float* gB = g_wn + (size_t)o0 * DIN;

    // Loader mapping: chunk id c in [0,1024): row = c>>3 (0..127), cg = c&7
    // (8 chunks of 4 consecutive k). Each thread owns 4 chunks per matrix.
    const int lr0 = tid >> 3;            // rows handled: lr0 + 32*i? no: chunks tid+i*256
    (void)lr0;

    float acc[8][8];
#pragma unroll
    for (int i = 0; i < 8; i++)
#pragma unroll
        for (int j = 0; j < 8; j++) acc[i][j] = 0.0f;

    float4 pa[4], pb[4];                 // prefetch registers

    // --- preload tile 0 into regs, store to buffer 0 ---
#pragma unroll
    for (int i = 0; i < 4; i++) {
        const int c = tid + i * 256;
        const int row = c >> 3, cg = c & 7;
        pa[i] = *(const float4*)(gA + (size_t)row * DIN + cg * 4);
        pb[i] = *(const float4*)(gB + (size_t)row * DIN + cg * 4);
    }
    {
        float* As = smem;
        float* Bs = smem + STAGE_FLOATS;
#pragma unroll
        for (int i = 0; i < 4; i++) {
            const int c = tid + i * 256;
            const int row = c >> 3, k = (c & 7) * 4;
            As[(k + 0) * 132 + row] = pa[i].x;
            As[(k + 1) * 132 + row] = pa[i].y;
            As[(k + 2) * 132 + row] = pa[i].z;
            As[(k + 3) * 132 + row] = pa[i].w;
            Bs[(k + 0) * 132 + row] = pb[i].x;
            Bs[(k + 1) * 132 + row] = pb[i].y;
            Bs[(k + 2) * 132 + row] = pb[i].z;
            Bs[(k + 3) * 132 + row] = pb[i].w;
        }
    }
    __syncthreads();

    for (int kt = 0; kt < KTILES; kt++) {
        // Prefetch next tile into registers (hidden under compute).
        if (kt + 1 < KTILES) {
            const int k0 = (kt + 1) * KC;
#pragma unroll
            for (int i = 0; i < 4; i++) {
                const int c = tid + i * 256;
                const int row = c >> 3, cg = c & 7;
                pa[i] = *(const float4*)(gA + (size_t)row * DIN + k0 + cg * 4);
                pb[i] = *(const float4*)(gB + (size_t)row * DIN + k0 + cg * 4);
            }
        }

        // Compute current buffer (k ascending — preserves the fma chain order).
        const float* As = smem + (kt & 1) * 2 * STAGE_FLOATS;
        const float* Bs = As + STAGE_FLOATS;
#pragma unroll
        for (int k = 0; k < KC; k++) {
            float a[8], b[8];
            *(float4*)&a[0] = *(const float4*)&As[k * 132 + rbase];
            *(float4*)&a[4] = *(const float4*)&As[k * 132 + rbase + 16];
            *(float4*)&b[0] = *(const float4*)&Bs[k * 132 + cbase];
            *(float4*)&b[4] = *(const float4*)&Bs[k * 132 + cbase + 32];
#pragma unroll
            for (int i = 0; i < 8; i++)
#pragma unroll
                for (int j = 0; j < 8; j++)
                    acc[i][j] = fmaf(a[i], b[j], acc[i][j]);
        }

        // Store prefetched tile into the other buffer; barrier.
        if (kt + 1 < KTILES) {
            float* Asn = smem + ((kt + 1) & 1) * 2 * STAGE_FLOATS;
            float* Bsn = Asn + STAGE_FLOATS;
#pragma unroll
            for (int i = 0; i < 4; i++) {
                const int c = tid + i * 256;
                const int row = c >> 3, k = (c & 7) * 4;
                Asn[(k + 0) * 132 + row] = pa[i].x;
                Asn[(k + 1) * 132 + row] = pa[i].y;
                Asn[(k + 2) * 132 + row] = pa[i].z;
                Asn[(k + 3) * 132 + row] = pa[i].w;
                Bsn[(k + 0) * 132 + row] = pb[i].x;
                Bsn[(k + 1) * 132 + row] = pb[i].y;
                Bsn[(k + 2) * 132 + row] = pb[i].z;
                Bsn[(k + 3) * 132 + row] = pb[i].w;
            }
        }
        __syncthreads();
    }

    // ---- Epilogue: stage [o_local][m_local] (pitch 129), then fused IF scan.
    float* stg = smem;                  // reuse pipeline smem (66048 <= 67584 B)
#pragma unroll
    for (int i = 0; i < 8; i++) {
        const int ml = rbase + (i & 3) + ((i >> 2) << 4);
#pragma unroll
        for (int j = 0; j < 8; j++) {
            const int ol = cbase + (j & 3) + ((j >> 2) << 5);
            stg[ol * STG_PITCH + ml] = acc[i][j];
        }
    }
    __syncthreads();

    // 256 tasks: o_l in [0,128) x n-group in {0,1}. m_l = nl*64 + t.
    const int ol = tid & 127;
    const int nl = tid >> 7;
    const int n  = (m0 >> 6) + nl;
    const int og = o0 + ol;
    const float bs = g_bstep[og];
    const float* col = stg + ol * STG_PITCH + nl * 64;
    float* so = spike_out + (size_t)n * TT * DOUT + og;

    float pot = 0.0f, cnt = 0.0f;
#pragma unroll 8
    for (int t = 0; t < TT; t++) {
        pot = (pot + col[t]) + bs;      // left-assoc, identical to R1 scan
        const float spk = (pot >= 1.0f) ? 1.0f : 0.0f;
        so[(size_t)t * DOUT] = spk;
        pot -= spk;
        cnt += spk;
    }
    count_out[(size_t)n * DOUT + og] = cnt;
}

// ---------------------------------------------------------------------------
// Launch
// ---------------------------------------------------------------------------
extern "C" void kernel_launch(void* const* d_in, const int* in_sizes, int n_in,
                              void* d_out, int out_size) {
    (void)in_sizes; (void)n_in; (void)out_size;

    const float* x_st  = (const float*)d_in[0];  // (512, 64, 1024) binary
    // d_in[1] unused (ANN path not returned)
    const float* w     = (const float*)d_in[2];
    const float* bias  = (const float*)d_in[3];
    const float* gamma = (const float*)d_in[4];
    const float* beta  = (const float*)d_in[5];
    const float* mean  = (const float*)d_in[6];
    const float* var   = (const float*)d_in[7];

    float* out       = (float*)d_out;
    float* spike_out = out;                                 // 512*64*1024
    float* count_out = out + (size_t)MTOT * DOUT;           // 512*1024

    prep_kernel<<<DOUT, 256>>>(w, bias, gamma, beta, mean, var);

    cudaFuncSetAttribute(gemm_if_kernel,
                         cudaFuncAttributeMaxDynamicSharedMemorySize, SMEM_BYTES);

    dim3 grid(MTOT / 128, DOUT / 128);                      // 256 x 8
    gemm_if_kernel<<<grid, 256, SMEM_BYTES>>>(x_st, spike_out, count_out);
}

// round 6
// speedup vs baseline: 1.2500x; 1.2500x over previous
#include <cuda_runtime.h>
#include <cstdint>

// ---------------------------------------------------------------------------
// Problem constants
// ---------------------------------------------------------------------------
#define NN    512
#define TT    64
#define DIN   1024
#define DOUT  1024
#define MTOT  (NN * TT)          // 32768

// GEMM tiling: CTA 128x128, 256 threads, 8x8/thread, KC=16, 4-stage cp.async.
#define KC      16
#define KTILES  (DIN / KC)       // 64
#define NSTAGE  4
#define STAGE_BYTES (KC * 128 * 4 * 2)     // A(8KB) + B(8KB) = 16384
#define STG_PITCH   129                    // epilogue staging [o:128][129][m:128]
#define SMEM_BYTES  66048                  // max(4*16384=65536, 128*129*4=66048)

// ---------------------------------------------------------------------------
// Device scratch (sanctioned: __device__ globals)
// ---------------------------------------------------------------------------
__device__ float g_at[(size_t)DIN * MTOT];  // 128 MB: A transposed [k][m]
__device__ float g_wt[DIN * DOUT];          // 4 MB: BN-folded W transposed [k][o]
__device__ float g_bstep[DOUT];

// ---------------------------------------------------------------------------
// Inline PTX
// ---------------------------------------------------------------------------
__device__ __forceinline__ uint32_t smem_to_u32(const void* p) {
    uint32_t a;
    asm("{ .reg .u64 t; cvta.to.shared.u64 t, %1; cvt.u32.u64 %0, t; }"
        : "=r"(a) : "l"(p));
    return a;
}

__device__ __forceinline__ void cpasync16(uint32_t s, const void* g) {
    asm volatile("cp.async.cg.shared.global [%0], [%1], 16;"
                 :: "r"(s), "l"(g) : "memory");
}

// ---------------------------------------------------------------------------
// Prep A: transpose A[m][k] -> At[k][m].  32x32 tiles, 32x8 threads.
// ---------------------------------------------------------------------------
__global__ __launch_bounds__(256)
void transpose_a_kernel(const float* __restrict__ A) {
    __shared__ float s[32][33];
    const int k0 = blockIdx.x * 32;          // 32 k-tiles
    const int m0 = blockIdx.y * 32;          // 1024 m-tiles
    const int tx = threadIdx.x, ty = threadIdx.y;
#pragma unroll
    for (int i = 0; i < 4; i++) {
        const int m = ty + i * 8;
        s[m][tx] = A[(size_t)(m0 + m) * DIN + k0 + tx];
    }
    __syncthreads();
#pragma unroll
    for (int i = 0; i < 4; i++) {
        const int k = ty + i * 8;
        g_at[(size_t)(k0 + k) * MTOT + m0 + tx] = s[tx][k];
    }
}

// ---------------------------------------------------------------------------
// Prep W: fold BN (ratio = gamma/sqrt(var), no eps — same arithmetic as R1)
// and transpose -> Wt[k][o]. Also compute b_step. 32x32 tiles.
// ---------------------------------------------------------------------------
__global__ __launch_bounds__(256)
void prep_w_kernel(const float* __restrict__ w,
                   const float* __restrict__ bias,
                   const float* __restrict__ gamma,
                   const float* __restrict__ beta,
                   const float* __restrict__ mean,
                   const float* __restrict__ var) {
    __shared__ float s[32][33];
    __shared__ float rat[32];
    const int k0 = blockIdx.x * 32;          // 32 k-tiles
    const int o0 = blockIdx.y * 32;          // 32 o-tiles
    const int tx = threadIdx.x, ty = threadIdx.y;
    if (ty == 0) {
        const int o = o0 + tx;
        const float ratio = gamma[o] / sqrtf(var[o]);
        rat[tx] = ratio;
        if (blockIdx.x == 0) {
            g_bstep[o] = ((bias[o] - mean[o]) * ratio + beta[o]) * (1.0f / (float)TT);
        }
    }
    __syncthreads();
#pragma unroll
    for (int i = 0; i < 4; i++) {
        const int oc = ty + i * 8;
        s[oc][tx] = w[(size_t)(o0 + oc) * DIN + k0 + tx] * rat[oc];
    }
    __syncthreads();
#pragma unroll
    for (int i = 0; i < 4; i++) {
        const int k = ty + i * 8;
        g_wt[(size_t)(k0 + k) * DOUT + o0 + tx] = s[tx][k];
    }
}

// ---------------------------------------------------------------------------
// Stage loader: cp.async straight into [k][row] layout (no transpose needed).
// A stage: KC x 128 floats at stage base; B stage: +8192 bytes.
// chunk c in [0,512): k = c>>5, cg = c&31  -> 16B at k*512 + cg*16.
// ---------------------------------------------------------------------------
__device__ __forceinline__ void load_stage(uint32_t sbu, int stage, int kt,
                                           int m0, int o0, int tid) {
    const uint32_t st = sbu + stage * STAGE_BYTES;
    const int k0 = kt * KC;
    const float* gA = g_at + (size_t)k0 * MTOT + m0;
    const float* gB = g_wt + (size_t)k0 * DOUT + o0;
#pragma unroll
    for (int i = 0; i < 2; i++) {
        const int c = tid + i * 256;
        const int k = c >> 5, cg = c & 31;
        cpasync16(st + k * 512 + cg * 16, gA + (size_t)k * MTOT + cg * 4);
        cpasync16(st + 8192 + k * 512 + cg * 16, gB + (size_t)k * DOUT + cg * 4);
    }
    asm volatile("cp.async.commit_group;" ::: "memory");
}

// ---------------------------------------------------------------------------
// Fused SGEMM + IF scan. fma chain: acc=0, k ascending, one fmaf per k
// (bit-identical to R1/R5 -> rel_err 8.103e-4 guaranteed).
// Warp layout as R1: 4x2 warps, rbase +0/+16, cbase +0/+32 (conflict-free).
// ---------------------------------------------------------------------------
__global__ __launch_bounds__(256, 2)
void gemm_if_kernel(float* __restrict__ spike_out,
                    float* __restrict__ count_out) {
    extern __shared__ __align__(16) float smem[];
    const uint32_t sbu = smem_to_u32(smem);

    const int tid  = threadIdx.x;
    const int warp = tid >> 5;
    const int lane = tid & 31;
    const int wr   = warp >> 1;
    const int wc   = warp & 1;
    const int rbase = wr * 32 + ((lane >> 3) << 2);
    const int cbase = wc * 64 + ((lane & 7) << 2);

    const int o0 = blockIdx.x * 128;        // 8 n-tiles (fast dim: B L2-resident)
    const int m0 = blockIdx.y * 128;        // 256 m-tiles

    float acc[8][8];
#pragma unroll
    for (int i = 0; i < 8; i++)
#pragma unroll
        for (int j = 0; j < 8; j++) acc[i][j] = 0.0f;

    // Prologue: issue NSTAGE-1 stages
    load_stage(sbu, 0, 0, m0, o0, tid);
    load_stage(sbu, 1, 1, m0, o0, tid);
    load_stage(sbu, 2, 2, m0, o0, tid);

    for (int kt = 0; kt < KTILES; kt++) {
        asm volatile("cp.async.wait_group 2;" ::: "memory");
        __syncthreads();

        if (kt + 3 < KTILES)
            load_stage(sbu, (kt + 3) & 3, kt + 3, m0, o0, tid);

        const float* As = smem + (kt & 3) * (STAGE_BYTES / 4);
        const float* Bs = As + 2048;

        // Fragment double-buffered FFMA loop (k ascending: chain preserved)
        float af[2][8], bf[2][8];
        *(float4*)&af[0][0] = *(const float4*)&As[rbase];
        *(float4*)&af[0][4] = *(const float4*)&As[rbase + 16];
        *(float4*)&bf[0][0] = *(const float4*)&Bs[cbase];
        *(float4*)&bf[0][4] = *(const float4*)&Bs[cbase + 32];
#pragma unroll
        for (int k = 0; k < KC; k++) {
            const int cur = k & 1, nxt = cur ^ 1;
            if (k + 1 < KC) {
                *(float4*)&af[nxt][0] = *(const float4*)&As[(k + 1) * 128 + rbase];
                *(float4*)&af[nxt][4] = *(const float4*)&As[(k + 1) * 128 + rbase + 16];
                *(float4*)&bf[nxt][0] = *(const float4*)&Bs[(k + 1) * 128 + cbase];
                *(float4*)&bf[nxt][4] = *(const float4*)&Bs[(k + 1) * 128 + cbase + 32];
            }
#pragma unroll
            for (int i = 0; i < 8; i++)
#pragma unroll
                for (int j = 0; j < 8; j++)
                    acc[i][j] = fmaf(af[cur][i], bf[cur][j], acc[i][j]);
        }
    }
    __syncthreads();   // all compute done before reusing smem for staging

    // ---- Epilogue: stage [o_local][m_local] (pitch 129), fused IF scan ----
    float* stg = smem;
#pragma unroll
    for (int i = 0; i < 8; i++) {
        const int ml = rbase + (i & 3) + ((i >> 2) << 4);
#pragma unroll
        for (int j = 0; j < 8; j++) {
            const int ol = cbase + (j & 3) + ((j >> 2) << 5);
            stg[ol * STG_PITCH + ml] = acc[i][j];
        }
    }
    __syncthreads();

    // 256 tasks: o_l in [0,128) x n-group {0,1}; m_l = nl*64 + t
    const int ol = tid & 127;
    const int nl = tid >> 7;
    const int n  = (m0 >> 6) + nl;
    const int og = o0 + ol;
    const float bs = g_bstep[og];
    const float* col = stg + ol * STG_PITCH + nl * 64;
    float* so = spike_out + (size_t)n * TT * DOUT + og;

    float pot = 0.0f, cnt = 0.0f;
#pragma unroll 8
    for (int t = 0; t < TT; t++) {
        pot = (pot + col[t]) + bs;          // left-assoc, identical to R1 scan
        const float spk = (pot >= 1.0f) ? 1.0f : 0.0f;
        so[(size_t)t * DOUT] = spk;
        pot -= spk;
        cnt += spk;
    }
    count_out[(size_t)n * DOUT + og] = cnt;
}

// ---------------------------------------------------------------------------
// Launch
// ---------------------------------------------------------------------------
extern "C" void kernel_launch(void* const* d_in, const int* in_sizes, int n_in,
                              void* d_out, int out_size) {
    (void)in_sizes; (void)n_in; (void)out_size;

    const float* x_st  = (const float*)d_in[0];  // (512, 64, 1024) binary
    const float* w     = (const float*)d_in[2];
    const float* bias  = (const float*)d_in[3];
    const float* gamma = (const float*)d_in[4];
    const float* beta  = (const float*)d_in[5];
    const float* mean  = (const float*)d_in[6];
    const float* var   = (const float*)d_in[7];

    float* out       = (float*)d_out;
    float* spike_out = out;                                 // 512*64*1024
    float* count_out = out + (size_t)MTOT * DOUT;           // 512*1024

    {
        dim3 blk(32, 8);
        dim3 grd(DIN / 32, MTOT / 32);                      // (32, 1024)
        transpose_a_kernel<<<grd, blk>>>(x_st);
        dim3 grd2(DIN / 32, DOUT / 32);                     // (32, 32)
        prep_w_kernel<<<grd2, blk>>>(w, bias, gamma, beta, mean, var);
    }

    cudaFuncSetAttribute(gemm_if_kernel,
                         cudaFuncAttributeMaxDynamicSharedMemorySize, SMEM_BYTES);

    dim3 grid(DOUT / 128, MTOT / 128);                      // (8, 256)
    gemm_if_kernel<<<grid, 256, SMEM_BYTES>>>(spike_out, count_out);
}